// round 9
// baseline (speedup 1.0000x reference)
#include <cuda_runtime.h>
#include <cuda_fp16.h>
#include <math.h>
#include <stdint.h>

#define B_   1024
#define H_   256
#define HP_  128
#define PHASE_W 8388608   // 256*32768 elements per phase
#define NSPLIT  8

// ---------------- scratch (static device arrays; no allocation) -------------
__device__ float  g_x3[B_ * HP_];           // [1024,128]
__device__ float  g_g1out[B_ * H_];         // [1024,256]
__device__ float  g_part[NSPLIT * B_ * H_]; // split-K partials, 8 MB

// ---------------- helpers ----------------------------------------------------
#define SWZ(o) ((o) ^ (((o) >> 3) & 0x70))

static __device__ __forceinline__ uint32_t smem_u32(const void* p) {
    return (uint32_t)__cvta_generic_to_shared(p);
}
static __device__ __forceinline__ uint32_t h2bits(__half2 h) {
    return *(uint32_t*)&h;
}

#define LDSM_X4(r, addr)                                                        \
    asm volatile("ldmatrix.sync.aligned.m8n8.x4.shared.b16 {%0,%1,%2,%3}, [%4];"\
        : "=r"((r)[0]), "=r"((r)[1]), "=r"((r)[2]), "=r"((r)[3]) : "r"(addr))

#define MMA16816(d, a, b0v, b1v)                                                \
    asm volatile("mma.sync.aligned.m16n8k16.row.col.f32.f16.f16.f32 "           \
        "{%0,%1,%2,%3}, {%4,%5,%6,%7}, {%8,%9}, {%0,%1,%2,%3};"                 \
        : "+f"((d)[0]), "+f"((d)[1]), "+f"((d)[2]), "+f"((d)[3])                \
        : "r"((a)[0]), "r"((a)[1]), "r"((a)[2]), "r"((a)[3]),                   \
          "r"(b0v), "r"(b1v))

// ---------------------------------------------------------------------------
// K0: blend + 3-layer tanh MLP -> x3. 4 batch rows per block, grid 256.
// ---------------------------------------------------------------------------
__global__ __launch_bounds__(128) void prep_kernel(
    const float* __restrict__ h0, const float* __restrict__ ht,
    const float* __restrict__ cp,
    const float* __restrict__ fc1, const float* __restrict__ fc2,
    const float* __restrict__ fc3, float* __restrict__ x3out)
{
    __shared__ float sh[4][256];
    __shared__ float s1[4][128];
    __shared__ float s2[4][128];
    const int t = threadIdx.x;
    const int b0 = blockIdx.x * 4;
    float cc = fminf(fmaxf(cp[0], 0.0f), 1.0f);
    for (int i = t; i < 4 * 256; i += 128) {
        int bb = i >> 8, j = i & 255;
        int g = (b0 + bb) * 256 + j;
        sh[bb][j] = cc * h0[g] + (1.0f - cc) * ht[g];
    }
    __syncthreads();
    {
        float acc[4] = {0, 0, 0, 0};
        const float4* wr = (const float4*)(fc1 + t * 256);
        #pragma unroll 8
        for (int j4 = 0; j4 < 64; ++j4) {
            float4 w = wr[j4]; int j = j4 * 4;
            #pragma unroll
            for (int bb = 0; bb < 4; ++bb)
                acc[bb] += w.x*sh[bb][j] + w.y*sh[bb][j+1] + w.z*sh[bb][j+2] + w.w*sh[bb][j+3];
        }
        #pragma unroll
        for (int bb = 0; bb < 4; ++bb) s1[bb][t] = tanhf(acc[bb]);
    }
    __syncthreads();
    {
        float acc[4] = {0, 0, 0, 0};
        const float4* wr = (const float4*)(fc2 + t * 128);
        #pragma unroll 8
        for (int j4 = 0; j4 < 32; ++j4) {
            float4 w = wr[j4]; int j = j4 * 4;
            #pragma unroll
            for (int bb = 0; bb < 4; ++bb)
                acc[bb] += w.x*s1[bb][j] + w.y*s1[bb][j+1] + w.z*s1[bb][j+2] + w.w*s1[bb][j+3];
        }
        #pragma unroll
        for (int bb = 0; bb < 4; ++bb) s2[bb][t] = tanhf(acc[bb]);
    }
    __syncthreads();
    {
        float acc[4] = {0, 0, 0, 0};
        const float4* wr = (const float4*)(fc3 + t * 128);
        #pragma unroll 8
        for (int j4 = 0; j4 < 32; ++j4) {
            float4 w = wr[j4]; int j = j4 * 4;
            #pragma unroll
            for (int bb = 0; bb < 4; ++bb)
                acc[bb] += w.x*s2[bb][j] + w.y*s2[bb][j+1] + w.z*s2[bb][j+2] + w.w*s2[bb][j+3];
        }
        #pragma unroll
        for (int bb = 0; bb < 4; ++bb)
            x3out[(b0 + bb) * 128 + t] = tanhf(acc[bb]);
    }
}

// ---------------------------------------------------------------------------
// Hyper-GEMM via mma.sync, fp16 with W 2-term hi/lo compensation.
//   part[ks][b0:b0+128, j0:j0+64] += A @ (Whi+Wlo)^T over this K split,
//   A[b, h*128+r] = left[b,h]*x3[b,r] synthesized in smem as fp16;
//   W read as fp32 and split hi/lo in the producer (no extra gmem traffic).
// Grid: 256 = 8 mt x 4 nt x 8 ks. K/split = 4096 = 64 chunks of 64.
// Block: 256 threads = 8 warps (2 M x 4 N; warp tile 64x16).
// 3 smem stages, one __syncthreads per chunk, 2 CTAs per SM.
// ---------------------------------------------------------------------------
#define ST_BYTES   32768          // A 16K | Whi 8K | Wlo 8K
#define A_OFF      0
#define WHI_OFF    16384
#define WLO_OFF    24576
#define LEFT_OFF   (3 * ST_BYTES)                 // [128][33] f32 = 16896 B
#define GEMM_SMEM  (LEFT_OFF + 128 * 33 * 4)      // 115200 B  (x2 CTA = 225 KB)

__global__ __launch_bounds__(256, 2) void hyper_gemm(
    const float* __restrict__ left,          // [1024,256]
    const float* __restrict__ x3g,           // [1024,128]
    const float* __restrict__ wf,            // fp32 [256][32768]
    float* __restrict__ part)                // [8][1024][256]
{
    extern __shared__ char smem[];
    const uint32_t smb = smem_u32(smem);
    const int t = threadIdx.x;

    const int mt = blockIdx.x & 7;
    const int nt = (blockIdx.x >> 3) & 3;
    const int ks = blockIdx.x >> 5;
    const int b0 = mt * 128;
    const int j0 = nt * 64;
    const int k_base = ks * 4096;
    const int h_base = ks * 32;

    float* s_left = (float*)(smem + LEFT_OFF);

    // ---- stage left slab [128][32] (pitch 33) ----
    #pragma unroll
    for (int u = 0; u < 4; ++u) {
        int id = u * 256 + t;                 // 1024 float4
        int r = id >> 3, c4 = id & 7;
        float4 v = *(const float4*)(left + (size_t)(b0 + r) * 256 + h_base + c4 * 4);
        float* dp = s_left + r * 33 + c4 * 4;
        dp[0] = v.x; dp[1] = v.y; dp[2] = v.z; dp[3] = v.w;
    }

    // ---- x3 -> registers as h2 (thread owns row t>>1, k-sub t&1) ----
    const int ar_row = t >> 1, ar_sub = t & 1;
    uint32_t xr[2][16];
    {
        const float* xsrc = x3g + (size_t)(b0 + ar_row) * 128 + ar_sub * 32;
        #pragma unroll
        for (int R = 0; R < 2; ++R)
            #pragma unroll
            for (int u = 0; u < 8; ++u) {
                float4 v = *(const float4*)(xsrc + R * 64 + u * 4);
                xr[R][u * 2]     = h2bits(__floats2half2_rn(v.x, v.y));
                xr[R][u * 2 + 1] = h2bits(__floats2half2_rn(v.z, v.w));
            }
    }
    __syncthreads();

    // ---- producer state: thread owns W row t>>2, 16-float slice (t&3)*16 ----
    const int wr_row = t >> 2;          // 0..63
    const int wr_f4  = t & 3;           // 0..3 (16-float slice)
    const float* wsrc_base = wf + (size_t)(j0 + wr_row) * 32768 + k_base + wr_f4 * 16;
    const uint32_t w_off0 = wr_row * 128 + wr_f4 * 32;   // bytes (fp16 row = 128 B)
    float wreg[16];

    #define LDG_W(c) do {                                                        \
        const float4* p = (const float4*)(wsrc_base + (c) * 64);                 \
        float4 v0 = p[0], v1 = p[1], v2 = p[2], v3 = p[3];                       \
        wreg[0]=v0.x;  wreg[1]=v0.y;  wreg[2]=v0.z;  wreg[3]=v0.w;               \
        wreg[4]=v1.x;  wreg[5]=v1.y;  wreg[6]=v1.z;  wreg[7]=v1.w;               \
        wreg[8]=v2.x;  wreg[9]=v2.y;  wreg[10]=v2.z; wreg[11]=v2.w;              \
        wreg[12]=v3.x; wreg[13]=v3.y; wreg[14]=v3.z; wreg[15]=v3.w;              \
    } while (0)

    #define STS_W(s2) do {                                                       \
        uint32_t hiw[8], low[8];                                                 \
        _Pragma("unroll")                                                        \
        for (int e = 0; e < 8; ++e) {                                            \
            float f0 = wreg[2*e], f1 = wreg[2*e+1];                              \
            __half ha = __float2half_rn(f0), hb = __float2half_rn(f1);           \
            __half la = __float2half_rn(f0 - __half2float(ha));                  \
            __half lb = __float2half_rn(f1 - __half2float(hb));                  \
            hiw[e] = h2bits(__halves2half2(ha, hb));                             \
            low[e] = h2bits(__halves2half2(la, lb));                             \
        }                                                                        \
        char* hb_ = smem + (s2)*ST_BYTES + WHI_OFF;                              \
        char* lb_ = smem + (s2)*ST_BYTES + WLO_OFF;                              \
        *(uint4*)(hb_ + SWZ(w_off0))      = make_uint4(hiw[0], hiw[1], hiw[2], hiw[3]); \
        *(uint4*)(hb_ + SWZ(w_off0 + 16)) = make_uint4(hiw[4], hiw[5], hiw[6], hiw[7]); \
        *(uint4*)(lb_ + SWZ(w_off0))      = make_uint4(low[0], low[1], low[2], low[3]); \
        *(uint4*)(lb_ + SWZ(w_off0 + 16)) = make_uint4(low[4], low[5], low[6], low[7]); \
    } while (0)

    #define GEN_A(c, s2) do {                                                    \
        const float L = s_left[ar_row * 33 + ((c) >> 1)];                        \
        const uint32_t* xp = xr[(c) & 1];                                        \
        char* ab = smem + (s2) * ST_BYTES + A_OFF;                               \
        _Pragma("unroll")                                                        \
        for (int g = 0; g < 4; ++g) {                                            \
            uint32_t o[4];                                                       \
            _Pragma("unroll")                                                    \
            for (int m = 0; m < 4; ++m) {                                        \
                float2 xf = __half22float2(*(__half2*)&xp[g * 4 + m]);           \
                o[m] = h2bits(__floats2half2_rn(L * xf.x, L * xf.y));            \
            }                                                                    \
            int off = ar_row * 128 + ar_sub * 64 + g * 16;                       \
            *(uint4*)(ab + SWZ(off)) = make_uint4(o[0], o[1], o[2], o[3]);       \
        }                                                                        \
    } while (0)

    // ---- consumer state: 8 warps = 2 M-warps x 4 N-warps ----
    const int wid = t >> 5, l = t & 31;
    const int mw = wid & 1;          // M-warp: rows mw*64..+64
    const int nw = wid >> 1;         // N-warp: cols nw*16..+16
    const uint32_t lrow = (uint32_t)(l & 15);
    const uint32_t lkb  = (uint32_t)((l >> 4) * 16);
    float d[4][2][4];
    #pragma unroll
    for (int mi = 0; mi < 4; ++mi)
        #pragma unroll
        for (int ni = 0; ni < 2; ++ni)
            #pragma unroll
            for (int e = 0; e < 4; ++e) d[mi][ni][e] = 0.0f;

    // ---- prologue: chunks 0,1 direct; prefetch chunk 2 ----
    LDG_W(0); STS_W(0); GEN_A(0, 0);
    LDG_W(1); STS_W(1); GEN_A(1, 1);
    LDG_W(2);

    // ---- mainloop: one barrier per chunk ----
    for (int c = 0; c < 64; ++c) {
        const int s = c % 3;
        __syncthreads();

        const uint32_t aB = smb + s * ST_BYTES + A_OFF;
        const uint32_t hB = smb + s * ST_BYTES + WHI_OFF;
        const uint32_t lB = smb + s * ST_BYTES + WLO_OFF;

        #pragma unroll
        for (int st = 0; st < 4; ++st) {
            const uint32_t kb = st * 32 + lkb;
            uint32_t bh[4], bl[4];
            {
                uint32_t off = (nw * 16 + lrow) * 128 + kb;
                LDSM_X4(bh, hB + SWZ(off));
                LDSM_X4(bl, lB + SWZ(off));
            }
            #pragma unroll
            for (int mi = 0; mi < 4; ++mi) {
                uint32_t a[4];
                uint32_t off = (mw * 64 + mi * 16 + lrow) * 128 + kb;
                LDSM_X4(a, aB + SWZ(off));
                #pragma unroll
                for (int ni = 0; ni < 2; ++ni) {
                    MMA16816(d[mi][ni], a, bh[ni], bh[ni + 2]);
                    MMA16816(d[mi][ni], a, bl[ni], bl[ni + 2]);
                }
            }
        }

        const int cn = c + 2;
        if (cn < 64) {
            const int s2 = cn % 3;
            STS_W(s2);           // wreg holds chunk cn (loaded last iter / prologue)
            GEN_A(cn, s2);
            if (cn + 1 < 64) LDG_W(cn + 1);
        }
    }

    // ---- epilogue: write fp32 partials ----
    {
        float* op = part + (size_t)ks * (B_ * H_);
        const int rb = b0 + mw * 64;
        const int cb = j0 + nw * 16;
        #pragma unroll
        for (int mi = 0; mi < 4; ++mi)
            #pragma unroll
            for (int ni = 0; ni < 2; ++ni) {
                int row = rb + mi * 16 + (l >> 2);
                int col = cb + ni * 8 + (l & 3) * 2;
                *(float2*)(op + (size_t)row * 256 + col) =
                    make_float2(d[mi][ni][0], d[mi][ni][1]);
                *(float2*)(op + (size_t)(row + 8) * 256 + col) =
                    make_float2(d[mi][ni][2], d[mi][ni][3]);
            }
    }
    #undef LDG_W
    #undef STS_W
    #undef GEN_A
}

// ---------------------------------------------------------------------------
// Split-K reduction over 8 partials (+ optional tanh)
// ---------------------------------------------------------------------------
template <bool TANH>
__global__ __launch_bounds__(256) void reduce8(
    const float* __restrict__ part, float* __restrict__ outp)
{
    const int total4 = (B_ * H_) / 4;   // 65536
    for (int i = blockIdx.x * blockDim.x + threadIdx.x; i < total4;
         i += gridDim.x * blockDim.x) {
        float4 r = ((const float4*)part)[i];
        #pragma unroll
        for (int s = 1; s < NSPLIT; ++s) {
            float4 v = ((const float4*)part)[i + s * 65536];
            r.x += v.x; r.y += v.y; r.z += v.z; r.w += v.w;
        }
        if (TANH) { r.x = tanhf(r.x); r.y = tanhf(r.y); r.z = tanhf(r.z); r.w = tanhf(r.w); }
        ((float4*)outp)[i] = r;
    }
}

// ---------------------------------------------------------------------------
extern "C" void kernel_launch(void* const* d_in, const int* in_sizes, int n_in,
                              void* d_out, int out_size)
{
    const float* h0  = (const float*)d_in[0];
    const float* ht  = (const float*)d_in[1];
    const float* msg = (const float*)d_in[2];
    const float* cp  = (const float*)d_in[3];
    const float* fc1 = (const float*)d_in[4];
    const float* fc2 = (const float*)d_in[5];
    const float* fc3 = (const float*)d_in[6];
    const float* fc4 = (const float*)d_in[7];
    float*       outp = (float*)d_out;

    float* x3p;  cudaGetSymbolAddress((void**)&x3p, g_x3);
    float* g1p;  cudaGetSymbolAddress((void**)&g1p, g_g1out);
    float* pp;   cudaGetSymbolAddress((void**)&pp,  g_part);

    cudaFuncSetAttribute(hyper_gemm, cudaFuncAttributeMaxDynamicSharedMemorySize,
                         GEMM_SMEM);

    // tanh chain -> x3
    prep_kernel<<<256, 128>>>(h0, ht, cp, fc1, fc2, fc3, x3p);
    // Phase A: g1_out = tanh(msg,x3 : W1)
    hyper_gemm<<<256, 256, GEMM_SMEM>>>(msg, x3p, fc4, pp);
    reduce8<true><<<256, 256>>>(pp, g1p);
    // Phase B: out = (g1_out,x3 : W2)
    hyper_gemm<<<256, 256, GEMM_SMEM>>>(g1p, x3p, fc4 + (size_t)PHASE_W, pp);
    reduce8<false><<<256, 256>>>(pp, outp);
}